// round 2
// baseline (speedup 1.0000x reference)
#include <cuda_runtime.h>
#include <cuda_bf16.h>

// Problem constants (fixed by setup_inputs: SIZE=161, MARGIN=3, BATCH=256, INPUT_SIZE=8)
#define PP      13041            // 161 * 81 grid2d points
#define BB      256              // batch
#define BZM     167              // padded grid dim (161 + 2*3)
#define GXX     84               // x extent (167//2 + 1)
#define BASE    83               // bz2 of padded grid
#define PLANE   (BZM * GXX)      // 14028
#define GRID_N  (BZM * BZM * GXX) // 2,342,676

// int32 copy of grid3d_index (input may arrive as int64 or int32 depending on
// the reference's JAX x64 config; we detect and convert). ~9.4 MB static.
__device__ int g_grid[GRID_N];
__device__ int g_is64;

__global__ void init_flag_k() { g_is64 = 1; }

// If the buffer is little-endian int64, every odd 32-bit word is the sign
// extension of its even neighbor, i.e. 0 or -1. Genuine int32 grid data has
// large positive indices at odd flat positions, so any violation proves int32.
// Reading the first GRID_N words is in-bounds for both dtypes.
__global__ void detect_k(const int* __restrict__ g) {
    int i = blockIdx.x * blockDim.x + threadIdx.x;
    if (i < GRID_N && (i & 1)) {
        int v = g[i];
        if (v != 0 && v != -1) g_is64 = 0;   // race-free: all writers store 0
    }
}

__global__ void convert_k(const void* __restrict__ gin) {
    int i = blockIdx.x * blockDim.x + threadIdx.x;
    if (i >= GRID_N) return;
    if (g_is64) g_grid[i] = (int)((const long long*)gin)[i];
    else        g_grid[i] = ((const int*)gin)[i];
}

__global__ __launch_bounds__(256)
void svr_main_k(const float* __restrict__ inp,   // [B,8]
                const float* __restrict__ W,     // [Wc,8,2]
                const float* __restrict__ Bi,    // [Wc,2]
                const float* __restrict__ R,     // [B,3,3]
                const float* __restrict__ C,     // [P,2]
                const int*   __restrict__ mrp,   // scalar max_r (low word valid for i32/i64)
                float*       __restrict__ out)   // [B,P,2]
{
    int p = blockIdx.x * blockDim.x + threadIdx.x;
    int b = blockIdx.y;
    if (p >= PP) return;

    float2 co = ((const float2*)C)[p];
    float2* o = (float2*)out + (size_t)b * PP + p;

    int mr = min(mrp[0], (BZM - 2 * 3) / 2);     // min(max_r, 80)
    float mr2 = (float)(mr * mr);
    if (co.x * co.x + co.y * co.y > mr2) {       // invalid -> exact zero
        *o = make_float2(0.f, 0.f);
        return;
    }

    const float* r = R + b * 9;
    float X = __ldg(r + 0) * co.x + __ldg(r + 1) * co.y;
    float Y = __ldg(r + 3) * co.x + __ldg(r + 4) * co.y;
    float Z = __ldg(r + 6) * co.x + __ldg(r + 7) * co.y;
    float sgn = 1.f;
    if (X < 0.f) { X = -X; Y = -Y; Z = -Z; sgn = -1.f; }

    float fx = floorf(X), fy = floorf(Y), fz = floorf(Z);
    float tx = X - fx, ty = Y - fy, tz = Z - fz;
    int xi = (int)fx;
    int yi = (int)fy + BASE;
    int zi = (int)fz + BASE;
    int gb = zi * PLANE + yi * GXX + xi;

    // All 8 corner indices up front for memory-level parallelism
    int jj[8];
    jj[0] = g_grid[gb];
    jj[1] = g_grid[gb + 1];
    jj[2] = g_grid[gb + GXX];
    jj[3] = g_grid[gb + GXX + 1];
    jj[4] = g_grid[gb + PLANE];
    jj[5] = g_grid[gb + PLANE + 1];
    jj[6] = g_grid[gb + PLANE + GXX];
    jj[7] = g_grid[gb + PLANE + GXX + 1];

    // Per-batch input vector (uniform across the block, broadcasts via L1)
    const float4* ip4 = (const float4*)(inp + b * 8);
    float4 i0 = __ldg(ip4);
    float4 i1 = __ldg(ip4 + 1);

    float wx[2] = {1.f - tx, tx};
    float wy[2] = {1.f - ty, ty};
    float wz[2] = {1.f - tz, tz};

    float a0 = 0.f, a1 = 0.f;
#pragma unroll
    for (int k = 0; k < 8; k++) {
        int j = jj[k];
        if (j < 0) continue;
        float wgt = wx[k & 1] * wy[(k >> 1) & 1] * wz[k >> 2];
        const float4* w4 = (const float4*)(W + (size_t)j * 16);
        float4 wa = __ldg(w4 + 0);   // d0c0 d0c1 d1c0 d1c1
        float4 wb = __ldg(w4 + 1);   // d2c0 d2c1 d3c0 d3c1
        float4 wc = __ldg(w4 + 2);   // d4c0 d4c1 d5c0 d5c1
        float4 wd = __ldg(w4 + 3);   // d6c0 d6c1 d7c0 d7c1
        float2 bs = __ldg((const float2*)(Bi + (size_t)j * 2));
        float v0 = fmaf(wa.x, i0.x, fmaf(wa.z, i0.y, fmaf(wb.x, i0.z, fmaf(wb.z, i0.w,
                   fmaf(wc.x, i1.x, fmaf(wc.z, i1.y, fmaf(wd.x, i1.z, fmaf(wd.z, i1.w, bs.x))))))));
        float v1 = fmaf(wa.y, i0.x, fmaf(wa.w, i0.y, fmaf(wb.y, i0.z, fmaf(wb.w, i0.w,
                   fmaf(wc.y, i1.x, fmaf(wc.w, i1.y, fmaf(wd.y, i1.z, fmaf(wd.w, i1.w, bs.y))))))));
        a0 = fmaf(wgt, v0, a0);
        a1 = fmaf(wgt, v1, a1);
    }

    *o = make_float2(a0, a1 * sgn);
}

extern "C" void kernel_launch(void* const* d_in, const int* in_sizes, int n_in,
                              void* d_out, int out_size) {
    const float* inp = (const float*)d_in[0];
    const float* W   = (const float*)d_in[1];
    const float* Bi  = (const float*)d_in[2];
    const void*  G   = d_in[3];
    const float* R   = (const float*)d_in[4];
    const float* C   = (const float*)d_in[5];
    const int*   mrp = (const int*)d_in[6];

    init_flag_k<<<1, 1>>>();
    int nb = (GRID_N + 255) / 256;
    detect_k<<<nb, 256>>>((const int*)G);
    convert_k<<<nb, 256>>>(G);

    dim3 grid((PP + 255) / 256, BB);
    svr_main_k<<<grid, 256>>>(inp, W, Bi, R, C, mrp, (float*)d_out);
}

// round 4
// speedup vs baseline: 1.0757x; 1.0757x over previous
#include <cuda_runtime.h>
#include <cuda_bf16.h>

// Problem constants (fixed by setup_inputs: SIZE=161, MARGIN=3, BATCH=256, INPUT_SIZE=8)
#define PP      13041             // 161 * 81 grid2d points
#define BB      256               // batch
#define BZM     167               // padded grid dim (161 + 2*3)
#define GXX     84                // x extent (167//2 + 1)
#define BASE    83                // bz2 of padded grid
#define PLANE   (BZM * GXX)       // 14028
#define GRID_N  (BZM * BZM * GXX) // 2,342,676

// int32 copy of grid3d_index (input may arrive as int64 or int32; detect + convert).
__device__ int g_grid[GRID_N];
__device__ int g_is64;

// If the buffer is little-endian int64, every odd 32-bit word is the sign
// extension of its even neighbor (0 or -1). Any other value proves int32.
__global__ void detect_k(const int* __restrict__ g) {
    int i = blockIdx.x * blockDim.x + threadIdx.x;
    if (i < GRID_N && (i & 1)) {
        int v = g[i];
        if (v != 0 && v != -1) g_is64 = 0;   // race-free: all writers store 0
    }
}

__global__ void convert_k(const void* __restrict__ gin) {
    int i = blockIdx.x * blockDim.x + threadIdx.x;
    if (i >= GRID_N) return;
    if (g_is64) g_grid[i] = (int)((const long long*)gin)[i];
    else        g_grid[i] = ((const int*)gin)[i];
}

// 4 lanes cooperate per point: lane q owns weight-row quarter q (16B) and
// input dims {2q, 2q+1}. Weight gather: one LDG.128 per corner covers 8
// points' full rows -> ~1 L1 line-access per point (was 4).
__global__ __launch_bounds__(256)
void svr_main_k(const float* __restrict__ inp,   // [B,8]
                const float* __restrict__ W,     // [Wc,8,2]
                const float* __restrict__ Bi,    // [Wc,2]
                const float* __restrict__ R,     // [B,3,3]
                const float* __restrict__ C,     // [P,2]
                const int*   __restrict__ mrp,   // scalar max_r
                float*       __restrict__ out)   // [B,P,2]
{
    int t   = blockIdx.x * blockDim.x + threadIdx.x;
    int p   = t >> 2;                 // point index
    int q   = threadIdx.x & 3;        // quad lane
    int b   = blockIdx.y;
    if (p >= PP) return;

    unsigned lane  = threadIdx.x & 31;
    unsigned qmask = 0xFu << (lane & ~3u);

    float2 co = ((const float2*)C)[p];
    float2* o = (float2*)out + (size_t)b * PP + p;

    int mr = min(mrp[0], (BZM - 2 * 3) / 2);     // min(max_r, 80)
    float mr2 = (float)(mr * mr);
    if (co.x * co.x + co.y * co.y > mr2) {       // invalid -> exact zero
        if (q == 0) *o = make_float2(0.f, 0.f);
        return;
    }

    const float* r = R + b * 9;
    float X = __ldg(r + 0) * co.x + __ldg(r + 1) * co.y;
    float Y = __ldg(r + 3) * co.x + __ldg(r + 4) * co.y;
    float Z = __ldg(r + 6) * co.x + __ldg(r + 7) * co.y;
    float sgn = 1.f;
    if (X < 0.f) { X = -X; Y = -Y; Z = -Z; sgn = -1.f; }

    float fx = floorf(X), fy = floorf(Y), fz = floorf(Z);
    float tx = X - fx, ty = Y - fy, tz = Z - fz;
    int xi = (int)fx;
    int yi = (int)fy + BASE;
    int zi = (int)fz + BASE;
    int gb = zi * PLANE + yi * GXX + xi;

    // Lane q loads index pair (dy = q&1, dz = q>>1): corners (dx=0), (dx=1).
    int pbase = gb + (q & 1) * GXX + (q >> 1) * PLANE;
    int j0 = g_grid[pbase];
    int j1 = g_grid[pbase + 1];

    // This lane's 2 input dims (uniform across block: L1 broadcast)
    float2 iv = __ldg((const float2*)(inp + b * 8 + 2 * q));

    float wx[2] = {1.f - tx, tx};
    float wy[2] = {1.f - ty, ty};
    float wz[2] = {1.f - tz, tz};

    float a0 = 0.f, a1 = 0.f;
#pragma unroll
    for (int k = 0; k < 8; k++) {
        int pair = k >> 1;           // dy + 2*dz
        int j = __shfl_sync(qmask, (k & 1) ? j1 : j0, pair, 4);
        if (j < 0) continue;
        float wgt = wx[k & 1] * wy[pair & 1] * wz[pair >> 1];
        // Lane q fetches its 16B quarter of row j (floats 4q..4q+3):
        //   (d=2q,c0) (d=2q,c1) (d=2q+1,c0) (d=2q+1,c1)
        float4 w = __ldg((const float4*)(W + (size_t)j * 16) + q);
        float v0 = fmaf(w.x, iv.x, w.z * iv.y);
        float v1 = fmaf(w.y, iv.x, w.w * iv.y);
        if (q == 0) {                // bias added exactly once per corner
            float2 bs = __ldg((const float2*)(Bi + (size_t)j * 2));
            v0 += bs.x;
            v1 += bs.y;
        }
        a0 = fmaf(wgt, v0, a0);
        a1 = fmaf(wgt, v1, a1);
    }

    // Reduce the 4 partial sums within the quad
    a0 += __shfl_xor_sync(qmask, a0, 1, 4);
    a0 += __shfl_xor_sync(qmask, a0, 2, 4);
    a1 += __shfl_xor_sync(qmask, a1, 1, 4);
    a1 += __shfl_xor_sync(qmask, a1, 2, 4);

    if (q == 0) *o = make_float2(a0, a1 * sgn);
}

extern "C" void kernel_launch(void* const* d_in, const int* in_sizes, int n_in,
                              void* d_out, int out_size) {
    const float* inp = (const float*)d_in[0];
    const float* W   = (const float*)d_in[1];
    const float* Bi  = (const float*)d_in[2];
    const void*  G   = d_in[3];
    const float* R   = (const float*)d_in[4];
    const float* C   = (const float*)d_in[5];
    const int*   mrp = (const int*)d_in[6];

    void* flag_addr = nullptr;
    cudaGetSymbolAddress(&flag_addr, g_is64);
    cudaMemsetAsync(flag_addr, 1, sizeof(int));   // truthy init (0x01010101)

    int nb = (GRID_N + 255) / 256;
    detect_k<<<nb, 256>>>((const int*)G);
    convert_k<<<nb, 256>>>(G);

    // 4 threads per point -> 64 points per 256-thread block
    dim3 grid((PP + 63) / 64, BB);
    svr_main_k<<<grid, 256>>>(inp, W, Bi, R, C, mrp, (float*)d_out);
}

// round 5
// speedup vs baseline: 1.4127x; 1.3133x over previous
#include <cuda_runtime.h>
#include <cuda_bf16.h>

// Problem constants (fixed by setup_inputs: SIZE=161, MARGIN=3, BATCH=256, INPUT_SIZE=8)
#define PP      13041             // 161 * 81 grid2d points
#define BB      256               // batch
#define BZM     167               // padded grid dim (161 + 2*3)
#define GXX     84                // x extent (167//2 + 1)
#define BASE    83                // bz2 of padded grid
#define PLANE   (BZM * GXX)       // 14028
#define GRID_N  (BZM * BZM * GXX) // 2,342,676 (even)

__device__ int g_is64;

// Dtype probe: for a little-endian int64 buffer every odd 32-bit word is the
// sign extension of its even neighbor (0 or -1). Any other value proves int32.
// Coalesced: each thread checks the high word of one aligned 8-byte pair.
__global__ void detect_k(const int2* __restrict__ g) {
    int i = blockIdx.x * blockDim.x + threadIdx.x;
    if (i < GRID_N / 2) {
        int v = g[i].y;
        if (v != 0 && v != -1) g_is64 = 0;   // race-free: all writers store 0
    }
}

// 4 lanes cooperate per point: lane q owns weight-row quarter q (16B) and
// input dims {2q, 2q+1}. One LDG.128 per corner per lane covers 8 points'
// full 64B rows. All corner loads are UNCONDITIONAL (clamped index + zeroed
// weight) so ptxas batches them -> MLP ~8 instead of serialized L2 latency.
__global__ __launch_bounds__(256, 4)
void svr_main_k(const float* __restrict__ inp,   // [B,8]
                const float* __restrict__ W,     // [Wc,8,2]
                const float* __restrict__ Bi,    // [Wc,2]
                const void*  __restrict__ Graw,  // [BZM,BZM,GXX] int32 or int64
                const float* __restrict__ R,     // [B,3,3]
                const float* __restrict__ C,     // [P,2]
                const int*   __restrict__ mrp,   // scalar max_r
                float*       __restrict__ out)   // [B,P,2]
{
    int t = blockIdx.x * blockDim.x + threadIdx.x;
    int p = t >> 2;                  // point index
    int q = threadIdx.x & 3;         // quad lane
    int b = blockIdx.y;
    if (p >= PP) return;

    unsigned lane  = threadIdx.x & 31;
    unsigned qmask = 0xFu << (lane & ~3u);

    float2 co = ((const float2*)C)[p];
    float2* o = (float2*)out + (size_t)b * PP + p;

    int mr = min(mrp[0], (BZM - 2 * 3) / 2);     // min(max_r, 80)
    float mr2 = (float)(mr * mr);
    if (co.x * co.x + co.y * co.y > mr2) {       // invalid -> exact zero
        if (q == 0) *o = make_float2(0.f, 0.f);
        return;
    }

    const float* r = R + b * 9;
    float X = __ldg(r + 0) * co.x + __ldg(r + 1) * co.y;
    float Y = __ldg(r + 3) * co.x + __ldg(r + 4) * co.y;
    float Z = __ldg(r + 6) * co.x + __ldg(r + 7) * co.y;
    float sgn = 1.f;
    if (X < 0.f) { X = -X; Y = -Y; Z = -Z; sgn = -1.f; }

    float fx = floorf(X), fy = floorf(Y), fz = floorf(Z);
    float tx = X - fx, ty = Y - fy, tz = Z - fz;
    int xi = (int)fx;
    int yi = (int)fy + BASE;
    int zi = (int)fz + BASE;
    int gb = zi * PLANE + yi * GXX + xi;

    // Lane q loads the index pair for (dy = q&1, dz = q>>1), dx in {0,1},
    // straight from the input buffer (uniform dtype branch, no convert pass).
    int pbase = gb + (q & 1) * GXX + (q >> 1) * PLANE;
    int j0, j1;
    if (g_is64) {
        const long long* g64 = (const long long*)Graw;
        j0 = (int)g64[pbase];
        j1 = (int)g64[pbase + 1];
    } else {
        const int* g32 = (const int*)Graw;
        j0 = g32[pbase];
        j1 = g32[pbase + 1];
    }

    // Broadcast all 8 corner indices across the quad BEFORE any weight load.
    int jc[8];
#pragma unroll
    for (int k = 0; k < 8; k++)
        jc[k] = __shfl_sync(qmask, (k & 1) ? j1 : j0, k >> 1, 4);

    // This lane's 2 input dims (uniform across block: L1 broadcast)
    float2 iv = __ldg((const float2*)(inp + b * 8 + 2 * q));

    float wx[2] = {1.f - tx, tx};
    float wy[2] = {1.f - ty, ty};
    float wz[2] = {1.f - tz, tz};

    float a0 = 0.f, a1 = 0.f;
#pragma unroll
    for (int k = 0; k < 8; k++) {
        int jr = jc[k];
        int j  = max(jr, 0);                               // clamped, safe
        float wgt = (jr >= 0) ? wx[k & 1] * wy[(k >> 1) & 1] * wz[k >> 2] : 0.f;
        // Lane q's 16B quarter of row j: (d=2q,c0)(d=2q,c1)(d=2q+1,c0)(d=2q+1,c1)
        float4 w = __ldg((const float4*)(W + (size_t)j * 16) + q);
        float v0 = fmaf(w.x, iv.x, w.z * iv.y);
        float v1 = fmaf(w.y, iv.x, w.w * iv.y);
        if (q == 0) {                                      // bias once per corner
            float2 bs = __ldg((const float2*)(Bi + (size_t)j * 2));
            v0 += bs.x;
            v1 += bs.y;
        }
        a0 = fmaf(wgt, v0, a0);
        a1 = fmaf(wgt, v1, a1);
    }

    // Reduce the 4 partial sums within the quad
    a0 += __shfl_xor_sync(qmask, a0, 1, 4);
    a0 += __shfl_xor_sync(qmask, a0, 2, 4);
    a1 += __shfl_xor_sync(qmask, a1, 1, 4);
    a1 += __shfl_xor_sync(qmask, a1, 2, 4);

    if (q == 0) *o = make_float2(a0, a1 * sgn);
}

extern "C" void kernel_launch(void* const* d_in, const int* in_sizes, int n_in,
                              void* d_out, int out_size) {
    const float* inp = (const float*)d_in[0];
    const float* W   = (const float*)d_in[1];
    const float* Bi  = (const float*)d_in[2];
    const void*  G   = d_in[3];
    const float* R   = (const float*)d_in[4];
    const float* C   = (const float*)d_in[5];
    const int*   mrp = (const int*)d_in[6];

    void* flag_addr = nullptr;
    cudaGetSymbolAddress(&flag_addr, g_is64);
    cudaMemsetAsync(flag_addr, 1, sizeof(int));   // truthy init (0x01010101)

    int nb = (GRID_N / 2 + 255) / 256;
    detect_k<<<nb, 256>>>((const int2*)G);

    // 4 threads per point -> 64 points per 256-thread block
    dim3 grid((PP + 63) / 64, BB);
    svr_main_k<<<grid, 256>>>(inp, W, Bi, G, R, C, mrp, (float*)d_out);
}

// round 9
// speedup vs baseline: 1.5069x; 1.0667x over previous
#include <cuda_runtime.h>
#include <cuda_bf16.h>

// Problem constants (fixed by setup_inputs: SIZE=161, MARGIN=3, BATCH=256, INPUT_SIZE=8)
#define PP      13041             // 161 * 81 grid2d points
#define BB      256               // batch
#define BZM     167               // padded grid dim (161 + 2*3)
#define GXX     84                // x extent (167//2 + 1)
#define BASE    83                // bz2 of padded grid
#define PLANE   (BZM * GXX)       // 14028
#define GRID_N  (BZM * BZM * GXX) // 2,342,676 (even)

__device__ int g_is64;
__device__ int g_cnt[2];          // [0]=n_valid, [1]=n_invalid
__device__ int g_vlist[PP];
__device__ int g_ilist[PP];

// Dtype probe: little-endian int64 => every odd 32-bit word is 0 or -1.
__global__ void detect_k(const int2* __restrict__ g) {
    int i = blockIdx.x * blockDim.x + threadIdx.x;
    if (i < GRID_N / 2) {
        int v = g[i].y;
        if (v != 0 && v != -1) g_is64 = 0;   // race-free: all writers store 0
    }
}

// Split points into valid (inside disc) / invalid lists. Append order is
// nondeterministic but each point's output is computed identically -> OK.
__global__ void compact_k(const float* __restrict__ C, const int* __restrict__ mrp) {
    int p = blockIdx.x * blockDim.x + threadIdx.x;
    if (p >= PP) return;
    float2 co = ((const float2*)C)[p];
    int mr = min(mrp[0], (BZM - 2 * 3) / 2);
    float mr2 = (float)(mr * mr);
    if (co.x * co.x + co.y * co.y <= mr2) {
        g_vlist[atomicAdd(&g_cnt[0], 1)] = p;
    } else {
        g_ilist[atomicAdd(&g_cnt[1], 1)] = p;
    }
}

// Zero outputs for invalid points (output buffer is poisoned each run).
__global__ void zero_k(float* __restrict__ out) {
    int i = blockIdx.x * blockDim.x + threadIdx.x;
    if (i >= g_cnt[1]) return;
    int p = g_ilist[i];
    ((float2*)out)[(size_t)blockIdx.y * PP + p] = make_float2(0.f, 0.f);
}

// 4 lanes per point; lane q owns weight-row quarter q (16B) and input dims
// {2q,2q+1}. Corners processed in two batches of 4 (dz=0 then dz=1) to keep
// register pressure at ~48 regs -> 5 CTAs/SM. Bias for corner q / 4+q is
// loaded by lane q (balanced scattered LDG.64s).
__global__ __launch_bounds__(256, 5)
void svr_main_k(const float* __restrict__ inp,   // [B,8]
                const float* __restrict__ W,     // [Wc,8,2]
                const float* __restrict__ Bi,    // [Wc,2]
                const void*  __restrict__ Graw,  // [BZM,BZM,GXX] int32 or int64
                const float* __restrict__ R,     // [B,3,3]
                const float* __restrict__ C,     // [P,2]
                float*       __restrict__ out)   // [B,P,2]
{
    int t    = blockIdx.x * blockDim.x + threadIdx.x;
    int slot = t >> 2;                // compacted point slot
    int q    = threadIdx.x & 3;       // quad lane
    int b    = blockIdx.y;
    if (slot >= g_cnt[0]) return;
    int p = g_vlist[slot];

    unsigned lane  = threadIdx.x & 31;
    unsigned qmask = 0xFu << (lane & ~3u);

    float2 co = ((const float2*)C)[p];

    const float* r = R + b * 9;
    float X = __ldg(r + 0) * co.x + __ldg(r + 1) * co.y;
    float Y = __ldg(r + 3) * co.x + __ldg(r + 4) * co.y;
    float Z = __ldg(r + 6) * co.x + __ldg(r + 7) * co.y;
    float sgn = 1.f;
    if (X < 0.f) { X = -X; Y = -Y; Z = -Z; sgn = -1.f; }

    float fx = floorf(X), fy = floorf(Y), fz = floorf(Z);
    float tx = X - fx, ty = Y - fy, tz = Z - fz;
    int xi = (int)fx;
    int yi = (int)fy + BASE;
    int zi = (int)fz + BASE;
    int gb = zi * PLANE + yi * GXX + xi;

    // Lane q loads the index pair for (dy = q&1, dz = q>>1), dx in {0,1}.
    int pbase = gb + (q & 1) * GXX + (q >> 1) * PLANE;
    int j0, j1;
    if (g_is64) {
        const long long* g64 = (const long long*)Graw;
        j0 = (int)g64[pbase];
        j1 = (int)g64[pbase + 1];
    } else {
        const int* g32 = (const int*)Graw;
        j0 = g32[pbase];
        j1 = g32[pbase + 1];
    }

    // This lane's 2 input dims (uniform across block: L1 broadcast)
    float2 iv = __ldg((const float2*)(inp + b * 8 + 2 * q));

    float wx[2] = {1.f - tx, tx};
    float wy[2] = {1.f - ty, ty};
    float wz[2] = {1.f - tz, tz};

    float a0 = 0.f, a1 = 0.f;

#pragma unroll
    for (int half = 0; half < 2; half++) {       // dz = half
        // Corners 4*half .. 4*half+3 ; pair source lanes 2*half, 2*half+1
        int jc[4];
#pragma unroll
        for (int k = 0; k < 4; k++)
            jc[k] = __shfl_sync(qmask, (k & 1) ? j1 : j0, 2 * half + (k >> 1), 4);

        // Unconditional clamped loads -> batched, MLP 5 per thread
        float4 wv[4];
#pragma unroll
        for (int k = 0; k < 4; k++)
            wv[k] = __ldg((const float4*)(W + (size_t)max(jc[k], 0) * 16) + q);
        float2 bs = __ldg((const float2*)(Bi + (size_t)max(jc[q], 0) * 2));

#pragma unroll
        for (int k = 0; k < 4; k++) {
            float wgt = (jc[k] >= 0) ? wx[k & 1] * wy[k >> 1] * wz[half] : 0.f;
            float v0 = fmaf(wv[k].x, iv.x, wv[k].z * iv.y);
            float v1 = fmaf(wv[k].y, iv.x, wv[k].w * iv.y);
            a0 = fmaf(wgt, v0, a0);
            a1 = fmaf(wgt, v1, a1);
        }
        // Bias for corner (4*half + q), exactly once per corner across the quad
        float wb = (jc[q] >= 0) ? wx[q & 1] * wy[q >> 1] * wz[half] : 0.f;
        a0 = fmaf(wb, bs.x, a0);
        a1 = fmaf(wb, bs.y, a1);
    }

    // Reduce the 4 partial sums within the quad
    a0 += __shfl_xor_sync(qmask, a0, 1, 4);
    a0 += __shfl_xor_sync(qmask, a0, 2, 4);
    a1 += __shfl_xor_sync(qmask, a1, 1, 4);
    a1 += __shfl_xor_sync(qmask, a1, 2, 4);

    if (q == 0)
        ((float2*)out)[(size_t)b * PP + p] = make_float2(a0, a1 * sgn);
}

extern "C" void kernel_launch(void* const* d_in, const int* in_sizes, int n_in,
                              void* d_out, int out_size) {
    const float* inp = (const float*)d_in[0];
    const float* W   = (const float*)d_in[1];
    const float* Bi  = (const float*)d_in[2];
    const void*  G   = d_in[3];
    const float* R   = (const float*)d_in[4];
    const float* C   = (const float*)d_in[5];
    const int*   mrp = (const int*)d_in[6];

    void* addr = nullptr;
    cudaGetSymbolAddress(&addr, g_is64);
    cudaMemsetAsync(addr, 1, sizeof(int));        // truthy init (0x01010101)
    cudaGetSymbolAddress(&addr, g_cnt);
    cudaMemsetAsync(addr, 0, 2 * sizeof(int));

    int nb = (GRID_N / 2 + 255) / 256;
    detect_k<<<nb, 256>>>((const int2*)G);
    compact_k<<<(PP + 255) / 256, 256>>>(C, mrp);

    dim3 zgrid((PP + 255) / 256, BB);
    zero_k<<<zgrid, 256>>>((float*)d_out);

    // 4 threads per point -> 64 points per 256-thread block (worst-case grid)
    dim3 grid((PP + 63) / 64, BB);
    svr_main_k<<<grid, 256>>>(inp, W, Bi, G, R, C, (float*)d_out);
}

// round 12
// speedup vs baseline: 1.8645x; 1.2373x over previous
#include <cuda_runtime.h>
#include <cuda_bf16.h>

// Problem constants (fixed by setup_inputs: SIZE=161, MARGIN=3, BATCH=256, INPUT_SIZE=8)
#define PP      13041             // 161 * 81 grid2d points
#define BB      256               // batch
#define BZM     167               // padded grid dim (161 + 2*3)
#define GXX     84                // x extent (167//2 + 1)
#define BASE    83                // bz2 of padded grid
#define PLANE   (BZM * GXX)       // 14028
#define GRID_N  (BZM * BZM * GXX) // 2,342,676

// Probe word: flat int32-word index of voxel (z=83,y=83,x=1) = ball interior.
// int32 buffer -> large positive index there; int64 buffer -> this word is the
// high half of element 585648, whose value fits in int32 -> word is 0 (or -1).
#define PROBE_W 1171297

__device__ int g_is64;
__device__ int g_cnt[2];          // [0]=n_valid, [1]=n_invalid
__device__ int g_vlist[PP];
__device__ int g_ilist[PP];

// Single-load dtype probe + counter reset (1 thread).
__global__ void detect_k(const int* __restrict__ g) {
    g_cnt[0] = 0;
    g_cnt[1] = 0;
    int v = g[PROBE_W];
    g_is64 = (v == 0 || v == -1) ? 1 : 0;
}

// Split points into valid (inside disc) / invalid lists. Append order is
// nondeterministic but each point's output is computed identically -> OK.
__global__ void compact_k(const float* __restrict__ C, const int* __restrict__ mrp) {
    int p = blockIdx.x * blockDim.x + threadIdx.x;
    if (p >= PP) return;
    float2 co = ((const float2*)C)[p];
    int mr = min(mrp[0], (BZM - 2 * 3) / 2);
    float mr2 = (float)(mr * mr);
    if (co.x * co.x + co.y * co.y <= mr2) {
        g_vlist[atomicAdd(&g_cnt[0], 1)] = p;
    } else {
        g_ilist[atomicAdd(&g_cnt[1], 1)] = p;
    }
}

// 4 lanes per point; lane q owns weight-row quarter q (16B) and input dims
// {2q,2q+1}. One LDG.128 per corner per lane covers 8 points' full 64B rows.
// Corners in two batches of 4 (dz=0/1); all loads unconditional (clamped
// offset + zeroed trilinear weight) so they batch -> MLP ~5/thread.
// Tail slots (>= n_valid) zero-fill the invalid points' outputs.
__global__ __launch_bounds__(256, 6)
void svr_main_k(const float* __restrict__ inp,   // [B,8]
                const float* __restrict__ W,     // [Wc,8,2]
                const float* __restrict__ Bi,    // [Wc,2]
                const void*  __restrict__ Graw,  // [BZM,BZM,GXX] int32 or int64
                const float* __restrict__ R,     // [B,3,3]
                const float* __restrict__ C,     // [P,2]
                float*       __restrict__ out)   // [B,P,2]
{
    int t    = blockIdx.x * blockDim.x + threadIdx.x;
    int slot = t >> 2;                // compacted point slot
    int q    = threadIdx.x & 3;       // quad lane
    int b    = blockIdx.y;
    if (slot >= PP) return;

    int nvalid = g_cnt[0];
    if (slot >= nvalid) {             // invalid point: exact-zero output
        if (q == 0) {
            int p = g_ilist[slot - nvalid];
            ((float2*)out)[(size_t)b * PP + p] = make_float2(0.f, 0.f);
        }
        return;
    }
    int p = g_vlist[slot];

    unsigned lane  = threadIdx.x & 31;
    unsigned qmask = 0xFu << (lane & ~3u);

    float2 co = ((const float2*)C)[p];

    const float* r = R + b * 9;
    float X = __ldg(r + 0) * co.x + __ldg(r + 1) * co.y;
    float Y = __ldg(r + 3) * co.x + __ldg(r + 4) * co.y;
    float Z = __ldg(r + 6) * co.x + __ldg(r + 7) * co.y;
    float sgn = 1.f;
    if (X < 0.f) { X = -X; Y = -Y; Z = -Z; sgn = -1.f; }

    float fx = floorf(X), fy = floorf(Y), fz = floorf(Z);
    float tx = X - fx, ty = Y - fy, tz = Z - fz;
    int xi = (int)fx;
    int yi = (int)fy + BASE;
    int zi = (int)fz + BASE;
    int gb = zi * PLANE + yi * GXX + xi;

    // Lane q loads the index pair for (dy = q&1, dz = q>>1), dx in {0,1}.
    int pbase = gb + (q & 1) * GXX + (q >> 1) * PLANE;
    int j0, j1;
    if (g_is64) {
        const long long* g64 = (const long long*)Graw;
        j0 = (int)g64[pbase];
        j1 = (int)g64[pbase + 1];
    } else {
        const int* g32 = (const int*)Graw;
        j0 = g32[pbase];
        j1 = g32[pbase + 1];
    }

    // This lane's 2 input dims (uniform across block: L1 broadcast)
    float2 iv = __ldg((const float2*)(inp + b * 8 + 2 * q));

    float wx[2] = {1.f - tx, tx};
    float wy[2] = {1.f - ty, ty};
    float wz[2] = {1.f - tz, tz};

    const char* Wb  = (const char*)W;
    const char* Bib = (const char*)Bi;

    float a0 = 0.f, a1 = 0.f;

#pragma unroll
    for (int half = 0; half < 2; half++) {       // dz = half
        // Corner k (k = dx + 2*dy): index from lane (2*half + dy)'s pair.
        unsigned off[4];
        float    wg[4];
#pragma unroll
        for (int k = 0; k < 4; k++) {
            int j = __shfl_sync(qmask, (k & 1) ? j1 : j0, 2 * half + (k >> 1), 4);
            wg[k]  = (j >= 0) ? wx[k & 1] * wy[k >> 1] * wz[half] : 0.f;
            off[k] = (unsigned)max(j, 0) * 64u;  // byte offset of row j
        }

        // Unconditional batched loads (5 in flight incl. bias)
        float4 wv0 = __ldg((const float4*)(Wb + off[0]) + q);
        float4 wv1 = __ldg((const float4*)(Wb + off[1]) + q);
        float4 wv2 = __ldg((const float4*)(Wb + off[2]) + q);
        float4 wv3 = __ldg((const float4*)(Wb + off[3]) + q);
        float2 bs  = __ldg((const float2*)(Bib + (off[q] >> 3)));  // row q's bias

        a0 = fmaf(wg[0], fmaf(wv0.x, iv.x, wv0.z * iv.y), a0);
        a1 = fmaf(wg[0], fmaf(wv0.y, iv.x, wv0.w * iv.y), a1);
        a0 = fmaf(wg[1], fmaf(wv1.x, iv.x, wv1.z * iv.y), a0);
        a1 = fmaf(wg[1], fmaf(wv1.y, iv.x, wv1.w * iv.y), a1);
        a0 = fmaf(wg[2], fmaf(wv2.x, iv.x, wv2.z * iv.y), a0);
        a1 = fmaf(wg[2], fmaf(wv2.y, iv.x, wv2.w * iv.y), a1);
        a0 = fmaf(wg[3], fmaf(wv3.x, iv.x, wv3.z * iv.y), a0);
        a1 = fmaf(wg[3], fmaf(wv3.y, iv.x, wv3.w * iv.y), a1);

        // Bias for corner q of this half, exactly once per corner across quad
        a0 = fmaf(wg[q], bs.x, a0);
        a1 = fmaf(wg[q], bs.y, a1);
    }

    // Reduce the 4 partial sums within the quad
    a0 += __shfl_xor_sync(qmask, a0, 1, 4);
    a0 += __shfl_xor_sync(qmask, a0, 2, 4);
    a1 += __shfl_xor_sync(qmask, a1, 1, 4);
    a1 += __shfl_xor_sync(qmask, a1, 2, 4);

    if (q == 0)
        ((float2*)out)[(size_t)b * PP + p] = make_float2(a0, a1 * sgn);
}

extern "C" void kernel_launch(void* const* d_in, const int* in_sizes, int n_in,
                              void* d_out, int out_size) {
    const float* inp = (const float*)d_in[0];
    const float* W   = (const float*)d_in[1];
    const float* Bi  = (const float*)d_in[2];
    const void*  G   = d_in[3];
    const float* R   = (const float*)d_in[4];
    const float* C   = (const float*)d_in[5];
    const int*   mrp = (const int*)d_in[6];

    detect_k<<<1, 1>>>((const int*)G);
    compact_k<<<(PP + 255) / 256, 256>>>(C, mrp);

    // 4 threads per point -> 64 points per 256-thread block (covers all PP
    // slots; tail slots zero-fill invalid points)
    dim3 grid((PP + 63) / 64, BB);
    svr_main_k<<<grid, 256>>>(inp, W, Bi, G, R, C, (float*)d_out);
}